// round 1
// baseline (speedup 1.0000x reference)
#include <cuda_runtime.h>
#include <math.h>
#include <float.h>

#define D_MODEL 1024
#define N_HEADS 16
#define D_H 64
#define BATCH 4
#define SEQ 2048
#define M_ROWS (BATCH * SEQ)   // 8192

// Scratch (alloc-free rule: __device__ globals)
__device__ float g_Q[M_ROWS * D_MODEL];
__device__ float g_K[M_ROWS * D_MODEL];
__device__ float g_V[M_ROWS * D_MODEL];
__device__ float g_Y[M_ROWS * D_MODEL];

// ---------------------------------------------------------------------------
// SGEMM: C[m][n] = sum_k A[m][k] * B[n][k] + bias[n]
// A: (M,1024) row-major, B: (1024,1024) row-major (torch Linear weight),
// i.e. an NT GEMM where both operands are K-contiguous.
// 128x128 CTA tile, BK=8, 256 threads, 8x8 per thread (2x2 blocks of 4x4).
// ---------------------------------------------------------------------------
__global__ __launch_bounds__(256) void sgemm_nt_bias(
    const float* __restrict__ A, const float* __restrict__ B,
    const float* __restrict__ bias, float* __restrict__ C)
{
    const int K = 1024, N = 1024;
    __shared__ float As[8][132];   // [k][m], padded for conflict-free STS/LDS
    __shared__ float Bs[8][132];   // [k][n]

    int tid = threadIdx.x;
    int bm = blockIdx.y * 128;
    int bn = blockIdx.x * 128;

    int lrow = tid >> 1;          // 0..127
    int lcol = (tid & 1) << 2;    // 0 or 4
    const float* Ag = A + (size_t)(bm + lrow) * K + lcol;
    const float* Bg = B + (size_t)(bn + lrow) * K + lcol;

    int tx = tid & 15;            // 0..15
    int ty = tid >> 4;            // 0..15

    float acc[8][8];
#pragma unroll
    for (int i = 0; i < 8; i++)
#pragma unroll
        for (int j = 0; j < 8; j++) acc[i][j] = 0.f;

    float4 a4 = *(const float4*)Ag;
    float4 b4 = *(const float4*)Bg;

    for (int kt = 0; kt < K; kt += 8) {
        As[lcol + 0][lrow] = a4.x; As[lcol + 1][lrow] = a4.y;
        As[lcol + 2][lrow] = a4.z; As[lcol + 3][lrow] = a4.w;
        Bs[lcol + 0][lrow] = b4.x; Bs[lcol + 1][lrow] = b4.y;
        Bs[lcol + 2][lrow] = b4.z; Bs[lcol + 3][lrow] = b4.w;
        __syncthreads();

        if (kt + 8 < K) {
            a4 = *(const float4*)(Ag + kt + 8);
            b4 = *(const float4*)(Bg + kt + 8);
        }

#pragma unroll
        for (int k = 0; k < 8; k++) {
            float ar[8], br[8];
            *(float4*)&ar[0] = *(const float4*)&As[k][ty * 4];
            *(float4*)&ar[4] = *(const float4*)&As[k][64 + ty * 4];
            *(float4*)&br[0] = *(const float4*)&Bs[k][tx * 4];
            *(float4*)&br[4] = *(const float4*)&Bs[k][64 + tx * 4];
#pragma unroll
            for (int i = 0; i < 8; i++)
#pragma unroll
                for (int j = 0; j < 8; j++)
                    acc[i][j] += ar[i] * br[j];
        }
        __syncthreads();
    }

    // Epilogue: bias add + store
#pragma unroll
    for (int i = 0; i < 8; i++) {
        int row = bm + ((i < 4) ? (ty * 4 + i) : (64 + ty * 4 + (i - 4)));
        float* Crow = C + (size_t)row * N + bn;
#pragma unroll
        for (int jj = 0; jj < 2; jj++) {
            int colb = (jj == 0) ? (tx * 4) : (64 + tx * 4);
            float4 bv = *(const float4*)(bias + bn + colb);
            float4 v;
            v.x = acc[i][jj * 4 + 0] + bv.x;
            v.y = acc[i][jj * 4 + 1] + bv.y;
            v.z = acc[i][jj * 4 + 2] + bv.z;
            v.w = acc[i][jj * 4 + 3] + bv.w;
            *(float4*)(Crow + colb) = v;
        }
    }
}

// ---------------------------------------------------------------------------
// Causal flash attention. Q/K/V in (B, T, H*64) layout (natural projection
// output). One CTA = 128 query rows of one (b,h); one thread = one query row.
// K/V tiles of 64 keys staged in SMEM; online softmax in 32-key chunks.
// ---------------------------------------------------------------------------
__global__ __launch_bounds__(128) void attention_kernel(
    const float* __restrict__ Q, const float* __restrict__ K,
    const float* __restrict__ V, const unsigned char* __restrict__ pad,
    float* __restrict__ Y)
{
    __shared__ float Ks[64 * 68];          // row stride 68 floats (pad)
    __shared__ float Vs[64 * 68];
    __shared__ unsigned char pads[64];

    int tid = threadIdx.x;                 // 0..127
    int qtile = blockIdx.x;                // 0..15
    int h = blockIdx.y;                    // 0..15
    int b = blockIdx.z;                    // 0..3
    int qrow = qtile * 128 + tid;

    const float* qptr = Q + ((size_t)(b * SEQ + qrow)) * D_MODEL + h * D_H;
    float qr[64];
#pragma unroll
    for (int d4 = 0; d4 < 16; d4++) {
        float4 v = *(const float4*)(qptr + d4 * 4);
        qr[d4 * 4 + 0] = v.x * 0.125f;     // 1/sqrt(64)
        qr[d4 * 4 + 1] = v.y * 0.125f;
        qr[d4 * 4 + 2] = v.z * 0.125f;
        qr[d4 * 4 + 3] = v.w * 0.125f;
    }

    float o[64];
#pragma unroll
    for (int d = 0; d < 64; d++) o[d] = 0.f;
    float m = -FLT_MAX;
    float l = 0.f;

    int nkt = 2 * qtile + 2;               // key tiles needed (causal)
    for (int kt = 0; kt < nkt; kt++) {
        const float* Kg = K + ((size_t)(b * SEQ + kt * 64)) * D_MODEL + h * D_H;
        const float* Vg = V + ((size_t)(b * SEQ + kt * 64)) * D_MODEL + h * D_H;
        __syncthreads();   // previous tile fully consumed
#pragma unroll
        for (int i = 0; i < 8; i++) {
            int f = tid + i * 128;         // 0..1023 float4 slots
            int r = f >> 4;
            int c4 = (f & 15) << 2;
            *(float4*)&Ks[r * 68 + c4] = *(const float4*)(Kg + r * D_MODEL + c4);
            *(float4*)&Vs[r * 68 + c4] = *(const float4*)(Vg + r * D_MODEL + c4);
        }
        if (tid < 64) pads[tid] = pad[b * SEQ + kt * 64 + tid];
        __syncthreads();

#pragma unroll
        for (int c0 = 0; c0 < 64; c0 += 32) {
            float s[32];
            float mx = m;
#pragma unroll
            for (int k = 0; k < 32; k++) {
                const float* kr = &Ks[(c0 + k) * 68];
                float acc = 0.f;
#pragma unroll
                for (int d4 = 0; d4 < 16; d4++) {
                    float4 kv = *(const float4*)(kr + d4 * 4);
                    acc += qr[d4 * 4 + 0] * kv.x + qr[d4 * 4 + 1] * kv.y
                         + qr[d4 * 4 + 2] * kv.z + qr[d4 * 4 + 3] * kv.w;
                }
                int kk = kt * 64 + c0 + k;
                if (kk > qrow || pads[c0 + k]) acc = -FLT_MAX;
                s[k] = acc;
                mx = fmaxf(mx, acc);
            }
            float scale = __expf(m - mx);
            l *= scale;
#pragma unroll
            for (int d = 0; d < 64; d++) o[d] *= scale;
            m = mx;
#pragma unroll
            for (int k = 0; k < 32; k++) {
                float p = __expf(s[k] - mx);
                l += p;
                const float* vr = &Vs[(c0 + k) * 68];
#pragma unroll
                for (int d4 = 0; d4 < 16; d4++) {
                    float4 vv = *(const float4*)(vr + d4 * 4);
                    o[d4 * 4 + 0] += p * vv.x;
                    o[d4 * 4 + 1] += p * vv.y;
                    o[d4 * 4 + 2] += p * vv.z;
                    o[d4 * 4 + 3] += p * vv.w;
                }
            }
        }
    }

    float inv = 1.f / l;
    float* yptr = Y + ((size_t)(b * SEQ + qrow)) * D_MODEL + h * D_H;
#pragma unroll
    for (int d4 = 0; d4 < 16; d4++) {
        float4 v;
        v.x = o[d4 * 4 + 0] * inv;
        v.y = o[d4 * 4 + 1] * inv;
        v.z = o[d4 * 4 + 2] * inv;
        v.w = o[d4 * 4 + 3] * inv;
        *(float4*)(yptr + d4 * 4) = v;
    }
}

// ---------------------------------------------------------------------------
extern "C" void kernel_launch(void* const* d_in, const int* in_sizes, int n_in,
                              void* d_out, int out_size)
{
    const float*         x   = (const float*)d_in[0];
    const unsigned char* pad = (const unsigned char*)d_in[1];
    const float*         Wq  = (const float*)d_in[2];
    const float*         bq  = (const float*)d_in[3];
    const float*         Wk  = (const float*)d_in[4];
    const float*         bk  = (const float*)d_in[5];
    const float*         Wv  = (const float*)d_in[6];
    const float*         bv  = (const float*)d_in[7];
    const float*         Wo  = (const float*)d_in[8];
    const float*         bo  = (const float*)d_in[9];
    float*               out = (float*)d_out;

    void *qp, *kp, *vp, *yp;
    cudaGetSymbolAddress(&qp, g_Q);
    cudaGetSymbolAddress(&kp, g_K);
    cudaGetSymbolAddress(&vp, g_V);
    cudaGetSymbolAddress(&yp, g_Y);
    float* Qs = (float*)qp;
    float* Kss = (float*)kp;
    float* Vss = (float*)vp;
    float* Ys = (float*)yp;

    dim3 gemm_grid(D_MODEL / 128, M_ROWS / 128);   // (8, 64)
    sgemm_nt_bias<<<gemm_grid, 256>>>(x, Wq, bq, Qs);
    sgemm_nt_bias<<<gemm_grid, 256>>>(x, Wk, bk, Kss);
    sgemm_nt_bias<<<gemm_grid, 256>>>(x, Wv, bv, Vss);

    dim3 attn_grid(SEQ / 128, N_HEADS, BATCH);     // (16, 16, 4)
    attention_kernel<<<attn_grid, 128>>>(Qs, Kss, Vss, pad, Ys);

    sgemm_nt_bias<<<gemm_grid, 256>>>(Ys, Wo, bo, out);
}

// round 8
// speedup vs baseline: 1.3932x; 1.3932x over previous
#include <cuda_runtime.h>
#include <cuda_bf16.h>
#include <math.h>
#include <float.h>
#include <stdint.h>

#define D_MODEL 1024
#define N_HEADS 16
#define D_H 64
#define BATCH 4
#define SEQ 2048
#define M_ROWS (BATCH * SEQ)   // 8192
#define K3 3072                // 3-term split K: [hi|lo|hi] . [hi|hi|lo]

// ---------------- scratch (__device__ globals; alloc-free rule) -------------
__device__ float g_Q[M_ROWS * D_MODEL];
__device__ float g_K[M_ROWS * D_MODEL];
__device__ float g_V[M_ROWS * D_MODEL];
__device__ float g_Y[M_ROWS * D_MODEL];
__device__ __nv_bfloat16 g_X3[M_ROWS * K3];
__device__ __nv_bfloat16 g_Y3[M_ROWS * K3];
__device__ __nv_bfloat16 g_W3q[D_MODEL * K3];
__device__ __nv_bfloat16 g_W3k[D_MODEL * K3];
__device__ __nv_bfloat16 g_W3v[D_MODEL * K3];
__device__ __nv_bfloat16 g_W3o[D_MODEL * K3];

// ---------------- PTX helpers (family-common features only) -----------------
__device__ __forceinline__ uint32_t smem_u32(const void* p) {
    uint32_t a;
    asm("{ .reg .u64 t; cvta.to.shared.u64 t, %1; cvt.u32.u64 %0, t; }" : "=r"(a) : "l"(p));
    return a;
}
__device__ __forceinline__ void cp_async16(uint32_t dst, const void* src) {
    asm volatile("cp.async.cg.shared.global [%0], [%1], 16;" :: "r"(dst), "l"(src) : "memory");
}
__device__ __forceinline__ void cp_commit() {
    asm volatile("cp.async.commit_group;" ::: "memory");
}
template <int N> __device__ __forceinline__ void cp_wait() {
    asm volatile("cp.async.wait_group %0;" :: "n"(N) : "memory");
}
__device__ __forceinline__ void ldmatrix_x4(uint32_t& r0, uint32_t& r1, uint32_t& r2, uint32_t& r3,
                                            uint32_t addr) {
    asm volatile("ldmatrix.sync.aligned.m8n8.x4.shared.b16 {%0,%1,%2,%3}, [%4];"
                 : "=r"(r0), "=r"(r1), "=r"(r2), "=r"(r3) : "r"(addr));
}
__device__ __forceinline__ void mma_16816(float& d0, float& d1, float& d2, float& d3,
                                          uint32_t a0, uint32_t a1, uint32_t a2, uint32_t a3,
                                          uint32_t b0, uint32_t b1) {
    asm volatile(
        "mma.sync.aligned.m16n8k16.row.col.f32.bf16.bf16.f32 "
        "{%0,%1,%2,%3}, {%4,%5,%6,%7}, {%8,%9}, {%0,%1,%2,%3};"
        : "+f"(d0), "+f"(d1), "+f"(d2), "+f"(d3)
        : "r"(a0), "r"(a1), "r"(a2), "r"(a3), "r"(b0), "r"(b1));
}

// ---------------- 3-term hi/lo conversion ------------------------------------
// mode 0 (A side): out row = [hi | lo | hi]
// mode 1 (B side): out row = [hi | hi | lo]
__global__ __launch_bounds__(256) void convert_hilo3(const float* __restrict__ in,
                                                     __nv_bfloat16* __restrict__ out,
                                                     int mode) {
    int idx4 = blockIdx.x * blockDim.x + threadIdx.x;
    int row = idx4 >> 8;
    int col = (idx4 & 255) << 2;
    float4 f = *(const float4*)(in + ((size_t)row << 10) + col);
    __nv_bfloat16 h[4], l[4];
    h[0] = __float2bfloat16(f.x); l[0] = __float2bfloat16(f.x - __bfloat162float(h[0]));
    h[1] = __float2bfloat16(f.y); l[1] = __float2bfloat16(f.y - __bfloat162float(h[1]));
    h[2] = __float2bfloat16(f.z); l[2] = __float2bfloat16(f.z - __bfloat162float(h[2]));
    h[3] = __float2bfloat16(f.w); l[3] = __float2bfloat16(f.w - __bfloat162float(h[3]));
    __nv_bfloat16* base = out + (size_t)row * K3 + col;
#pragma unroll
    for (int i = 0; i < 4; i++) {
        base[i] = h[i];
        if (mode == 0) { base[1024 + i] = l[i]; base[2048 + i] = h[i]; }
        else           { base[1024 + i] = h[i]; base[2048 + i] = l[i]; }
    }
}

// ---------------- mma.sync bf16 NT GEMM --------------------------------------
// C[m][n] = sum_k A3[m][k]*B3[n][k] + bias[n].  A3:(8192,3072) B3:(1024,3072) bf16.
// CTA 128x128, BK=64 (128B swizzled rows), 3-stage cp.async, 8 warps @ 32x64.
#define GTM 128
#define GTN 128
#define GKC 64
#define NCHUNK (K3 / GKC)          // 48
#define A_ST (GTM * 128)           // 16384 B
#define B_ST (GTN * 128)           // 16384 B
#define STAGE_BYTES (A_ST + B_ST)  // 32768
#define NSTAGE 3
#define GEMM_SMEM (NSTAGE * STAGE_BYTES + 1024)

extern __shared__ char dyn_smem[];

__global__ __launch_bounds__(256, 2)
void gemm_bf16_mma(const __nv_bfloat16* __restrict__ A3,
                   const __nv_bfloat16* __restrict__ Bq,
                   const __nv_bfloat16* __restrict__ Bk,
                   const __nv_bfloat16* __restrict__ Bv,
                   const float* __restrict__ biasq,
                   const float* __restrict__ biask,
                   const float* __restrict__ biasv,
                   float* __restrict__ Cq, float* __restrict__ Ck, float* __restrict__ Cv)
{
    const __nv_bfloat16* B3;
    const float* bias;
    float* C;
    if (blockIdx.z == 0)      { B3 = Bq; bias = biasq; C = Cq; }
    else if (blockIdx.z == 1) { B3 = Bk; bias = biask; C = Ck; }
    else                      { B3 = Bv; bias = biasv; C = Cv; }

    uint32_t smem_base = smem_u32(dyn_smem);
    uint32_t data0 = (smem_base + 1023) & ~1023u;

    int tid = threadIdx.x;
    int wid = tid >> 5;
    int lane = tid & 31;
    int bm = blockIdx.y * GTM;
    int bn = blockIdx.x * GTN;
    int wm = (wid & 3) * 32;       // warp m offset
    int wn = (wid >> 2) * 64;      // warp n offset

    int ar = lane & 15;            // A row within 16
    int ac = lane >> 4;            // A k-chunk select
    int n_off = ((lane >> 4) << 3) + (lane & 7);   // B n row within 16
    int kb = (lane >> 3) & 1;                      // B k-chunk select

    float d[2][8][4];
#pragma unroll
    for (int i = 0; i < 2; i++)
#pragma unroll
        for (int j = 0; j < 8; j++)
#pragma unroll
            for (int q = 0; q < 4; q++) d[i][j][q] = 0.f;

    auto load_chunk = [&](int c, int s) {
        uint32_t abase = data0 + s * STAGE_BYTES;
        uint32_t bbase = abase + A_ST;
        const __nv_bfloat16* Ac = A3 + (size_t)bm * K3 + c * GKC;
        const __nv_bfloat16* Bc = B3 + (size_t)bn * K3 + c * GKC;
#pragma unroll
        for (int t = 0; t < 4; t++) {
            int sgi = tid + t * 256;
            int row = sgi >> 3, seg = sgi & 7;
            cp_async16(abase + row * 128 + ((seg ^ (row & 7)) << 4),
                       Ac + (size_t)row * K3 + seg * 8);
        }
#pragma unroll
        for (int t = 0; t < 4; t++) {
            int sgi = tid + t * 256;
            int row = sgi >> 3, seg = sgi & 7;
            cp_async16(bbase + row * 128 + ((seg ^ (row & 7)) << 4),
                       Bc + (size_t)row * K3 + seg * 8);
        }
        cp_commit();
    };

    load_chunk(0, 0);
    load_chunk(1, 1);

    for (int i = 0; i < NCHUNK; i++) {
        int s = i % NSTAGE;
        if (i == NCHUNK - 1) cp_wait<0>(); else cp_wait<1>();
        __syncthreads();
        if (i + 2 < NCHUNK) load_chunk(i + 2, (i + 2) % NSTAGE);

        uint32_t abase = data0 + s * STAGE_BYTES;
        uint32_t bbase = abase + A_ST;
#pragma unroll
        for (int ks = 0; ks < 4; ks++) {
            uint32_t af[2][4];
#pragma unroll
            for (int mf = 0; mf < 2; mf++) {
                int row = wm + mf * 16 + ar;
                uint32_t addr = abase + row * 128 + (((ks * 2 + ac) ^ (ar & 7)) << 4);
                ldmatrix_x4(af[mf][0], af[mf][1], af[mf][2], af[mf][3], addr);
            }
#pragma unroll
            for (int nf = 0; nf < 4; nf++) {
                int row = wn + nf * 16 + n_off;
                uint32_t addr = bbase + row * 128 + (((ks * 2 + kb) ^ (n_off & 7)) << 4);
                uint32_t b00, b01, b10, b11;
                ldmatrix_x4(b00, b01, b10, b11, addr);
#pragma unroll
                for (int mf = 0; mf < 2; mf++) {
                    mma_16816(d[mf][2 * nf][0], d[mf][2 * nf][1], d[mf][2 * nf][2], d[mf][2 * nf][3],
                              af[mf][0], af[mf][1], af[mf][2], af[mf][3], b00, b01);
                    mma_16816(d[mf][2 * nf + 1][0], d[mf][2 * nf + 1][1], d[mf][2 * nf + 1][2], d[mf][2 * nf + 1][3],
                              af[mf][0], af[mf][1], af[mf][2], af[mf][3], b10, b11);
                }
            }
        }
        __syncthreads();
    }

#pragma unroll
    for (int mf = 0; mf < 2; mf++) {
        int m0 = bm + wm + mf * 16 + (lane >> 2);
#pragma unroll
        for (int n8 = 0; n8 < 8; n8++) {
            int n0 = bn + wn + n8 * 8 + (lane & 3) * 2;
            float b0 = bias[n0], b1 = bias[n0 + 1];
            float2 v0 = make_float2(d[mf][n8][0] + b0, d[mf][n8][1] + b1);
            float2 v1 = make_float2(d[mf][n8][2] + b0, d[mf][n8][3] + b1);
            *(float2*)(C + (size_t)m0 * D_MODEL + n0) = v0;
            *(float2*)(C + (size_t)(m0 + 8) * D_MODEL + n0) = v1;
        }
    }
}

// ---------------- fp32 flash attention, 2 threads per query ------------------
// 256 threads, 128 queries per CTA. Thread t: query t>>1, dim half (t&1)*32.
// Partial dot reduced with shfl_xor(1); both lanes keep identical softmax state.
__global__ __launch_bounds__(256, 2) void attention_kernel(
    const float* __restrict__ Q, const float* __restrict__ K,
    const float* __restrict__ V, const unsigned char* __restrict__ pad,
    float* __restrict__ Y)
{
    __shared__ float Ks[64 * 68];
    __shared__ float Vs[64 * 68];
    __shared__ unsigned char pads[64];

    int tid = threadIdx.x;                 // 0..255
    int qtile = blockIdx.x;
    int h = blockIdx.y;
    int b = blockIdx.z;
    int ql = tid >> 1;                     // 0..127
    int hf = tid & 1;                      // dim half
    int qrow = qtile * 128 + ql;

    const float* qptr = Q + ((size_t)(b * SEQ + qrow)) * D_MODEL + h * D_H + hf * 32;
    float qr[32];
#pragma unroll
    for (int d4 = 0; d4 < 8; d4++) {
        float4 v = *(const float4*)(qptr + d4 * 4);
        qr[d4 * 4 + 0] = v.x * 0.125f;
        qr[d4 * 4 + 1] = v.y * 0.125f;
        qr[d4 * 4 + 2] = v.z * 0.125f;
        qr[d4 * 4 + 3] = v.w * 0.125f;
    }

    float o[32];
#pragma unroll
    for (int d = 0; d < 32; d++) o[d] = 0.f;
    float m = -FLT_MAX;
    float l = 0.f;

    int nkt = 2 * qtile + 2;
    for (int kt = 0; kt < nkt; kt++) {
        const float* Kg = K + ((size_t)(b * SEQ + kt * 64)) * D_MODEL + h * D_H;
        const float* Vg = V + ((size_t)(b * SEQ + kt * 64)) * D_MODEL + h * D_H;
        __syncthreads();
#pragma unroll
        for (int i = 0; i < 4; i++) {
            int f = tid + i * 256;         // 0..1023 float4 slots
            int r = f >> 4;
            int c4 = (f & 15) << 2;
            *(float4*)&Ks[r * 68 + c4] = *(const float4*)(Kg + r * D_MODEL + c4);
            *(float4*)&Vs[r * 68 + c4] = *(const float4*)(Vg + r * D_MODEL + c4);
        }
        if (tid < 64) pads[tid] = pad[b * SEQ + kt * 64 + tid];
        __syncthreads();

#pragma unroll
        for (int c0 = 0; c0 < 64; c0 += 16) {
            float s[16];
            float mx = m;
#pragma unroll
            for (int k = 0; k < 16; k++) {
                const float* kr = &Ks[(c0 + k) * 68 + hf * 32];
                float acc = 0.f;
#pragma unroll
                for (int d4 = 0; d4 < 8; d4++) {
                    float4 kv = *(const float4*)(kr + d4 * 4);
                    acc += qr[d4 * 4 + 0] * kv.x + qr[d4 * 4 + 1] * kv.y
                         + qr[d4 * 4 + 2] * kv.z + qr[d4 * 4 + 3] * kv.w;
                }
                acc += __shfl_xor_sync(0xFFFFFFFFu, acc, 1);
                int kk = kt * 64 + c0 + k;
                if (kk > qrow || pads[c0 + k]) acc = -FLT_MAX;
                s[k] = acc;
                mx = fmaxf(mx, acc);
            }
            float scale = __expf(m - mx);
            l *= scale;
#pragma unroll
            for (int d = 0; d < 32; d++) o[d] *= scale;
            m = mx;
#pragma unroll
            for (int k = 0; k < 16; k++) {
                float p = __expf(s[k] - mx);
                l += p;
                const float* vr = &Vs[(c0 + k) * 68 + hf * 32];
#pragma unroll
                for (int d4 = 0; d4 < 8; d4++) {
                    float4 vv = *(const float4*)(vr + d4 * 4);
                    o[d4 * 4 + 0] += p * vv.x;
                    o[d4 * 4 + 1] += p * vv.y;
                    o[d4 * 4 + 2] += p * vv.z;
                    o[d4 * 4 + 3] += p * vv.w;
                }
            }
        }
    }

    float inv = 1.f / l;
    float* yptr = Y + ((size_t)(b * SEQ + qrow)) * D_MODEL + h * D_H + hf * 32;
#pragma unroll
    for (int d4 = 0; d4 < 8; d4++) {
        float4 v;
        v.x = o[d4 * 4 + 0] * inv;
        v.y = o[d4 * 4 + 1] * inv;
        v.z = o[d4 * 4 + 2] * inv;
        v.w = o[d4 * 4 + 3] * inv;
        *(float4*)(yptr + d4 * 4) = v;
    }
}

// ---------------------------------------------------------------------------
extern "C" void kernel_launch(void* const* d_in, const int* in_sizes, int n_in,
                              void* d_out, int out_size)
{
    const float*         x   = (const float*)d_in[0];
    const unsigned char* pad = (const unsigned char*)d_in[1];
    const float*         Wq  = (const float*)d_in[2];
    const float*         bq  = (const float*)d_in[3];
    const float*         Wk  = (const float*)d_in[4];
    const float*         bk  = (const float*)d_in[5];
    const float*         Wv  = (const float*)d_in[6];
    const float*         bv  = (const float*)d_in[7];
    const float*         Wo  = (const float*)d_in[8];
    const float*         bo  = (const float*)d_in[9];
    float*               out = (float*)d_out;

    void *qp, *kp, *vp, *yp, *x3p, *y3p, *wqp, *wkp, *wvp, *wop;
    cudaGetSymbolAddress(&qp, g_Q);
    cudaGetSymbolAddress(&kp, g_K);
    cudaGetSymbolAddress(&vp, g_V);
    cudaGetSymbolAddress(&yp, g_Y);
    cudaGetSymbolAddress(&x3p, g_X3);
    cudaGetSymbolAddress(&y3p, g_Y3);
    cudaGetSymbolAddress(&wqp, g_W3q);
    cudaGetSymbolAddress(&wkp, g_W3k);
    cudaGetSymbolAddress(&wvp, g_W3v);
    cudaGetSymbolAddress(&wop, g_W3o);
    float* Qs = (float*)qp;
    float* Kss = (float*)kp;
    float* Vss = (float*)vp;
    float* Ys = (float*)yp;
    __nv_bfloat16* X3 = (__nv_bfloat16*)x3p;
    __nv_bfloat16* Y3 = (__nv_bfloat16*)y3p;
    __nv_bfloat16* W3q = (__nv_bfloat16*)wqp;
    __nv_bfloat16* W3k = (__nv_bfloat16*)wkp;
    __nv_bfloat16* W3v = (__nv_bfloat16*)wvp;
    __nv_bfloat16* W3o = (__nv_bfloat16*)wop;

    cudaFuncSetAttribute(gemm_bf16_mma, cudaFuncAttributeMaxDynamicSharedMemorySize, GEMM_SMEM);

    convert_hilo3<<<(M_ROWS * 256) / 256, 256>>>(x, X3, 0);
    convert_hilo3<<<(D_MODEL * 256) / 256, 256>>>(Wq, W3q, 1);
    convert_hilo3<<<(D_MODEL * 256) / 256, 256>>>(Wk, W3k, 1);
    convert_hilo3<<<(D_MODEL * 256) / 256, 256>>>(Wv, W3v, 1);
    convert_hilo3<<<(D_MODEL * 256) / 256, 256>>>(Wo, W3o, 1);

    dim3 qkv_grid(D_MODEL / GTN, M_ROWS / GTM, 3);   // (8, 64, 3)
    gemm_bf16_mma<<<qkv_grid, 256, GEMM_SMEM>>>(
        X3, W3q, W3k, W3v, bq, bk, bv, Qs, Kss, Vss);

    dim3 attn_grid(SEQ / 128, N_HEADS, BATCH);       // (16, 16, 4)
    attention_kernel<<<attn_grid, 256>>>(Qs, Kss, Vss, pad, Ys);

    convert_hilo3<<<(M_ROWS * 256) / 256, 256>>>(Ys, Y3, 0);

    dim3 o_grid(D_MODEL / GTN, M_ROWS / GTM, 1);
    gemm_bf16_mma<<<o_grid, 256, GEMM_SMEM>>>(
        Y3, W3o, W3o, W3o, bo, bo, bo, out, out, out);
}

// round 10
// speedup vs baseline: 4.6782x; 3.3578x over previous
#include <cuda_runtime.h>
#include <cuda_bf16.h>
#include <math.h>
#include <float.h>
#include <stdint.h>

#define D_MODEL 1024
#define N_HEADS 16
#define D_H 64
#define BATCH 4
#define SEQ 2048
#define M_ROWS (BATCH * SEQ)   // 8192
#define K3 3072
#define LOG2E 1.4426950408889634f

// ---------------- scratch (__device__ globals; alloc-free rule) -------------
__device__ float g_V[M_ROWS * D_MODEL];
__device__ float g_Y[M_ROWS * D_MODEL];
__device__ __nv_bfloat16 g_Qhi[M_ROWS * D_MODEL];
__device__ __nv_bfloat16 g_Qlo[M_ROWS * D_MODEL];
__device__ __nv_bfloat16 g_Khi[M_ROWS * D_MODEL];
__device__ __nv_bfloat16 g_Klo[M_ROWS * D_MODEL];
__device__ __nv_bfloat16 g_VThi[BATCH * N_HEADS * D_H * SEQ];
__device__ __nv_bfloat16 g_VTlo[BATCH * N_HEADS * D_H * SEQ];
__device__ __nv_bfloat16 g_X3[M_ROWS * K3];
__device__ __nv_bfloat16 g_Y3[M_ROWS * K3];
__device__ __nv_bfloat16 g_W3q[D_MODEL * K3];
__device__ __nv_bfloat16 g_W3k[D_MODEL * K3];
__device__ __nv_bfloat16 g_W3v[D_MODEL * K3];
__device__ __nv_bfloat16 g_W3o[D_MODEL * K3];

// ---------------- PTX helpers ------------------------------------------------
__device__ __forceinline__ uint32_t smem_u32(const void* p) {
    uint32_t a;
    asm("{ .reg .u64 t; cvta.to.shared.u64 t, %1; cvt.u32.u64 %0, t; }" : "=r"(a) : "l"(p));
    return a;
}
__device__ __forceinline__ void cp_async16(uint32_t dst, const void* src) {
    asm volatile("cp.async.cg.shared.global [%0], [%1], 16;" :: "r"(dst), "l"(src) : "memory");
}
__device__ __forceinline__ void cp_async4(uint32_t dst, const void* src) {
    asm volatile("cp.async.ca.shared.global [%0], [%1], 4;" :: "r"(dst), "l"(src) : "memory");
}
__device__ __forceinline__ void cp_commit() {
    asm volatile("cp.async.commit_group;" ::: "memory");
}
template <int N> __device__ __forceinline__ void cp_wait() {
    asm volatile("cp.async.wait_group %0;" :: "n"(N) : "memory");
}
__device__ __forceinline__ void ldmatrix_x4(uint32_t& r0, uint32_t& r1, uint32_t& r2, uint32_t& r3,
                                            uint32_t addr) {
    asm volatile("ldmatrix.sync.aligned.m8n8.x4.shared.b16 {%0,%1,%2,%3}, [%4];"
                 : "=r"(r0), "=r"(r1), "=r"(r2), "=r"(r3) : "r"(addr));
}
__device__ __forceinline__ void mma_16816(float* d,
                                          uint32_t a0, uint32_t a1, uint32_t a2, uint32_t a3,
                                          uint32_t b0, uint32_t b1) {
    asm volatile(
        "mma.sync.aligned.m16n8k16.row.col.f32.bf16.bf16.f32 "
        "{%0,%1,%2,%3}, {%4,%5,%6,%7}, {%8,%9}, {%0,%1,%2,%3};"
        : "+f"(d[0]), "+f"(d[1]), "+f"(d[2]), "+f"(d[3])
        : "r"(a0), "r"(a1), "r"(a2), "r"(a3), "r"(b0), "r"(b1));
}
__device__ __forceinline__ uint32_t pack_bf16(float hi, float lo) {
    uint32_t d;
    asm("cvt.rn.bf16x2.f32 %0, %1, %2;" : "=r"(d) : "f"(hi), "f"(lo));
    return d;
}
// exp2 via FFMA only (no MUFU): t<=0 expected, clamps at -126.
__device__ __forceinline__ float exp2poly(float t) {
    t = fmaxf(t, -126.f);
    float r = t + 12582912.f;              // 1.5*2^23: round-to-int in mantissa
    int e = __float_as_int(r) - 0x4B400000;
    float f = t - (r - 12582912.f);        // f in [-0.5, 0.5]
    float p = 0.00133335581f;
    p = fmaf(p, f, 0.00961812911f);
    p = fmaf(p, f, 0.05550410866f);
    p = fmaf(p, f, 0.24022650695f);
    p = fmaf(p, f, 0.69314718056f);
    p = fmaf(p, f, 1.0f);
    return __int_as_float(__float_as_int(p) + (e << 23));
}

// ---------------- 3-term hi/lo conversion ------------------------------------
__global__ __launch_bounds__(256) void convert_hilo3(const float* __restrict__ in,
                                                     __nv_bfloat16* __restrict__ out,
                                                     int mode) {
    int idx4 = blockIdx.x * blockDim.x + threadIdx.x;
    int row = idx4 >> 8;
    int col = (idx4 & 255) << 2;
    float4 f = *(const float4*)(in + ((size_t)row << 10) + col);
    __nv_bfloat16 h[4], l[4];
    h[0] = __float2bfloat16(f.x); l[0] = __float2bfloat16(f.x - __bfloat162float(h[0]));
    h[1] = __float2bfloat16(f.y); l[1] = __float2bfloat16(f.y - __bfloat162float(h[1]));
    h[2] = __float2bfloat16(f.z); l[2] = __float2bfloat16(f.z - __bfloat162float(h[2]));
    h[3] = __float2bfloat16(f.w); l[3] = __float2bfloat16(f.w - __bfloat162float(h[3]));
    __nv_bfloat16* base = out + (size_t)row * K3 + col;
#pragma unroll
    for (int i = 0; i < 4; i++) {
        base[i] = h[i];
        if (mode == 0) { base[1024 + i] = l[i]; base[2048 + i] = h[i]; }
        else           { base[1024 + i] = h[i]; base[2048 + i] = l[i]; }
    }
}

// ---------------- V transpose + split: g_V -> VT hi/lo [bh][64][2048] --------
__global__ __launch_bounds__(256) void transpose_v(const float* __restrict__ V,
                                                   __nv_bfloat16* __restrict__ VThi,
                                                   __nv_bfloat16* __restrict__ VTlo) {
    __shared__ float ts[32][33];
    int tx = threadIdx.x & 31, ty = threadIdx.x >> 5;
    int t0 = blockIdx.x * 32, c0 = blockIdx.y * 32, b = blockIdx.z;
#pragma unroll
    for (int i = 0; i < 4; i++)
        ts[ty + i * 8][tx] = V[(size_t)(b * SEQ + t0 + ty + i * 8) * 1024 + c0 + tx];
    __syncthreads();
#pragma unroll
    for (int i = 0; i < 4; i++) {
        int dm = c0 + ty + i * 8;
        float v = ts[tx][ty + i * 8];
        __nv_bfloat16 h = __float2bfloat16(v);
        __nv_bfloat16 l = __float2bfloat16(v - __bfloat162float(h));
        size_t o = ((size_t)(b * 16 + (dm >> 6)) * 64 + (dm & 63)) * SEQ + t0 + tx;
        VThi[o] = h; VTlo[o] = l;
    }
}

// ---------------- mma.sync bf16 NT GEMM --------------------------------------
#define GTM 128
#define GTN 128
#define GKC 64
#define NCHUNK (K3 / GKC)
#define A_ST (GTM * 128)
#define B_ST (GTN * 128)
#define STAGE_BYTES (A_ST + B_ST)
#define NSTAGE 3
#define GEMM_SMEM (NSTAGE * STAGE_BYTES + 1024)

extern __shared__ char dyn_smem[];

__global__ __launch_bounds__(256, 2)
void gemm_bf16_mma(const __nv_bfloat16* __restrict__ A3,
                   const __nv_bfloat16* __restrict__ B0, const __nv_bfloat16* __restrict__ B1,
                   const __nv_bfloat16* __restrict__ B2w,
                   const float* __restrict__ bias0, const float* __restrict__ bias1,
                   const float* __restrict__ bias2,
                   float* cf0, float* cf1, float* cf2,
                   __nv_bfloat16* chi0, __nv_bfloat16* chi1, __nv_bfloat16* chi2,
                   __nv_bfloat16* clo0, __nv_bfloat16* clo1, __nv_bfloat16* clo2,
                   float sc0, float sc1, float sc2)
{
    const __nv_bfloat16* B3;
    const float* bias;
    float* cf; __nv_bfloat16 *chi, *clo; float scale;
    if (blockIdx.z == 0)      { B3 = B0; bias = bias0; cf = cf0; chi = chi0; clo = clo0; scale = sc0; }
    else if (blockIdx.z == 1) { B3 = B1; bias = bias1; cf = cf1; chi = chi1; clo = clo1; scale = sc1; }
    else                      { B3 = B2w; bias = bias2; cf = cf2; chi = chi2; clo = clo2; scale = sc2; }

    uint32_t smem_base = smem_u32(dyn_smem);
    uint32_t data0 = (smem_base + 1023) & ~1023u;

    int tid = threadIdx.x;
    int wid = tid >> 5;
    int lane = tid & 31;
    int bm = blockIdx.y * GTM;
    int bn = blockIdx.x * GTN;
    int wm = (wid & 3) * 32;
    int wn = (wid >> 2) * 64;

    int ar = lane & 15;
    int ac = lane >> 4;
    int n_off = ((lane >> 4) << 3) + (lane & 7);
    int kb = (lane >> 3) & 1;

    float d[2][8][4];
#pragma unroll
    for (int i = 0; i < 2; i++)
#pragma unroll
        for (int j = 0; j < 8; j++)
#pragma unroll
            for (int q = 0; q < 4; q++) d[i][j][q] = 0.f;

    auto load_chunk = [&](int c, int s) {
        uint32_t abase = data0 + s * STAGE_BYTES;
        uint32_t bbase = abase + A_ST;
        const __nv_bfloat16* Ac = A3 + (size_t)bm * K3 + c * GKC;
        const __nv_bfloat16* Bc = B3 + (size_t)bn * K3 + c * GKC;
#pragma unroll
        for (int t = 0; t < 4; t++) {
            int sgi = tid + t * 256;
            int row = sgi >> 3, seg = sgi & 7;
            cp_async16(abase + row * 128 + ((seg ^ (row & 7)) << 4),
                       Ac + (size_t)row * K3 + seg * 8);
        }
#pragma unroll
        for (int t = 0; t < 4; t++) {
            int sgi = tid + t * 256;
            int row = sgi >> 3, seg = sgi & 7;
            cp_async16(bbase + row * 128 + ((seg ^ (row & 7)) << 4),
                       Bc + (size_t)row * K3 + seg * 8);
        }
        cp_commit();
    };

    load_chunk(0, 0);
    load_chunk(1, 1);

    for (int i = 0; i < NCHUNK; i++) {
        int s = i % NSTAGE;
        if (i == NCHUNK - 1) cp_wait<0>(); else cp_wait<1>();
        __syncthreads();
        if (i + 2 < NCHUNK) load_chunk(i + 2, (i + 2) % NSTAGE);

        uint32_t abase = data0 + s * STAGE_BYTES;
        uint32_t bbase = abase + A_ST;
#pragma unroll
        for (int ks = 0; ks < 4; ks++) {
            uint32_t af[2][4];
#pragma unroll
            for (int mf = 0; mf < 2; mf++) {
                int row = wm + mf * 16 + ar;
                uint32_t addr = abase + row * 128 + (((ks * 2 + ac) ^ (ar & 7)) << 4);
                ldmatrix_x4(af[mf][0], af[mf][1], af[mf][2], af[mf][3], addr);
            }
#pragma unroll
            for (int nf = 0; nf < 4; nf++) {
                int row = wn + nf * 16 + n_off;
                uint32_t addr = bbase + row * 128 + (((ks * 2 + kb) ^ (n_off & 7)) << 4);
                uint32_t b00, b01, b10, b11;
                ldmatrix_x4(b00, b01, b10, b11, addr);
#pragma unroll
                for (int mf = 0; mf < 2; mf++) {
                    mma_16816(d[mf][2 * nf], af[mf][0], af[mf][1], af[mf][2], af[mf][3], b00, b01);
                    mma_16816(d[mf][2 * nf + 1], af[mf][0], af[mf][1], af[mf][2], af[mf][3], b10, b11);
                }
            }
        }
        __syncthreads();
    }

#pragma unroll
    for (int mf = 0; mf < 2; mf++) {
        int m0 = bm + wm + mf * 16 + (lane >> 2);
#pragma unroll
        for (int n8 = 0; n8 < 8; n8++) {
            int n0 = bn + wn + n8 * 8 + (lane & 3) * 2;
            float b0 = bias[n0], b1 = bias[n0 + 1];
            float v0 = (d[mf][n8][0] + b0) * scale;
            float v1 = (d[mf][n8][1] + b1) * scale;
            float v2 = (d[mf][n8][2] + b0) * scale;
            float v3 = (d[mf][n8][3] + b1) * scale;
            if (cf) {
                *(float2*)(cf + (size_t)m0 * D_MODEL + n0) = make_float2(v0, v1);
                *(float2*)(cf + (size_t)(m0 + 8) * D_MODEL + n0) = make_float2(v2, v3);
            }
            if (chi) {
                uint32_t h01 = pack_bf16(v1, v0);
                uint32_t h23 = pack_bf16(v3, v2);
                float r0 = v0 - __uint_as_float(h01 << 16);
                float r1 = v1 - __uint_as_float(h01 & 0xFFFF0000u);
                float r2 = v2 - __uint_as_float(h23 << 16);
                float r3 = v3 - __uint_as_float(h23 & 0xFFFF0000u);
                *(uint32_t*)(chi + (size_t)m0 * D_MODEL + n0) = h01;
                *(uint32_t*)(chi + (size_t)(m0 + 8) * D_MODEL + n0) = h23;
                *(uint32_t*)(clo + (size_t)m0 * D_MODEL + n0) = pack_bf16(r1, r0);
                *(uint32_t*)(clo + (size_t)(m0 + 8) * D_MODEL + n0) = pack_bf16(r3, r2);
            }
        }
    }
}

// ---------------- tensor-core flash attention --------------------------------
// CTA: 64 queries of one (b,h); 4 warps x 16 rows. 64-key tiles, 2-stage cp.async.
// smem: [0,8K) Qhi  [8K,16K) Qlo
//       stage s at 16K + s*32K: Khi, Klo, VThi, VTlo (8K each)
//       pads at 80K + s*64
#define AT_STAGE0 16384
#define AT_PADOFF (16384 + 65536)
#define AT_SMEM (AT_PADOFF + 128)

__global__ __launch_bounds__(128, 2)
void attention_mma(const __nv_bfloat16* __restrict__ Qhi, const __nv_bfloat16* __restrict__ Qlo,
                   const __nv_bfloat16* __restrict__ Khi, const __nv_bfloat16* __restrict__ Klo,
                   const __nv_bfloat16* __restrict__ VThi, const __nv_bfloat16* __restrict__ VTlo,
                   const unsigned char* __restrict__ pad, float* __restrict__ Y)
{
    uint32_t sb = smem_u32(dyn_smem);
    int tid = threadIdx.x;
    int wid = tid >> 5;
    int lane = tid & 31;
    int qt = (int)(gridDim.x - 1 - blockIdx.x);   // big tiles first
    int h = blockIdx.y, b = blockIdx.z;
    int nkt = qt + 1;

    int ar = lane & 15, ac = lane >> 4;
    int n_off = ((lane >> 4) << 3) + (lane & 7);
    int kb = (lane >> 3) & 1;

    // --- Q load (hi/lo), group 0
    {
        const __nv_bfloat16* srcs[2] = {Qhi, Qlo};
#pragma unroll
        for (int a = 0; a < 2; a++) {
            uint32_t base = sb + a * 8192;
            const __nv_bfloat16* src = srcs[a] + (size_t)(b * SEQ + qt * 64) * 1024 + h * 64;
#pragma unroll
            for (int t = 0; t < 4; t++) {
                int sgi = tid + t * 128;
                int row = sgi >> 3, seg = sgi & 7;
                cp_async16(base + row * 128 + ((seg ^ (row & 7)) << 4),
                           src + (size_t)row * 1024 + seg * 8);
            }
        }
        cp_commit();
    }

    auto load_tile = [&](int kt, int s) {
        uint32_t stb = sb + AT_STAGE0 + s * 32768;
        const __nv_bfloat16* ksrc[2] = {Khi, Klo};
#pragma unroll
        for (int a = 0; a < 2; a++) {
            uint32_t base = stb + a * 8192;
            const __nv_bfloat16* src = ksrc[a] + (size_t)(b * SEQ + kt * 64) * 1024 + h * 64;
#pragma unroll
            for (int t = 0; t < 4; t++) {
                int sgi = tid + t * 128;
                int row = sgi >> 3, seg = sgi & 7;
                cp_async16(base + row * 128 + ((seg ^ (row & 7)) << 4),
                           src + (size_t)row * 1024 + seg * 8);
            }
        }
        const __nv_bfloat16* vsrc[2] = {VThi, VTlo};
#pragma unroll
        for (int a = 0; a < 2; a++) {
            uint32_t base = stb + 16384 + a * 8192;
            const __nv_bfloat16* src = vsrc[a] + (size_t)(b * 16 + h) * 64 * SEQ + kt * 64;
#pragma unroll
            for (int t = 0; t < 4; t++) {
                int sgi = tid + t * 128;
                int row = sgi >> 3, seg = sgi & 7;
                cp_async16(base + row * 128 + ((seg ^ (row & 7)) << 4),
                           src + (size_t)row * SEQ + seg * 8);
            }
        }
        if (tid < 16)
            cp_async4(sb + AT_PADOFF + s * 64 + tid * 4, pad + b * SEQ + kt * 64 + tid * 4);
        cp_commit();
    };

    load_tile(0, 0);
    cp_wait<1>();            // Q done
    __syncthreads();

    // Q fragments
    uint32_t qa_h[4][4], qa_l[4][4];
#pragma unroll
    for (int kd = 0; kd < 4; kd++) {
        int row = wid * 16 + ar;
        uint32_t swz = (((kd * 2 + ac) ^ (ar & 7)) << 4);
        ldmatrix_x4(qa_h[kd][0], qa_h[kd][1], qa_h[kd][2], qa_h[kd][3], sb + row * 128 + swz);
        ldmatrix_x4(qa_l[kd][0], qa_l[kd][1], qa_l[kd][2], qa_l[kd][3], sb + 8192 + row * 128 + swz);
    }

    float o[8][4];
#pragma unroll
    for (int t = 0; t < 8; t++)
#pragma unroll
        for (int q = 0; q < 4; q++) o[t][q] = 0.f;
    float m2[2] = {-FLT_MAX, -FLT_MAX};
    float l2[2] = {0.f, 0.f};

    for (int kt = 0; kt < nkt; kt++) {
        int s = kt & 1;
        if (kt + 1 < nkt) { load_tile(kt + 1, s ^ 1); cp_wait<1>(); }
        else              { cp_wait<0>(); }
        __syncthreads();

        uint32_t kh_base = sb + AT_STAGE0 + s * 32768;
        uint32_t kl_base = kh_base + 8192;
        uint32_t vh_base = kh_base + 16384;
        uint32_t vl_base = kh_base + 24576;

        // ---- S = Q K^T (3-term)
        float c[8][4];
#pragma unroll
        for (int t = 0; t < 8; t++)
#pragma unroll
            for (int q = 0; q < 4; q++) c[t][q] = 0.f;
#pragma unroll
        for (int kd = 0; kd < 4; kd++) {
#pragma unroll
            for (int g = 0; g < 4; g++) {
                int row = g * 16 + n_off;
                uint32_t swz = (((kd * 2 + kb) ^ (n_off & 7)) << 4);
                uint32_t bh0, bh1, bh2, bh3, bl0, bl1, bl2, bl3;
                ldmatrix_x4(bh0, bh1, bh2, bh3, kh_base + row * 128 + swz);
                ldmatrix_x4(bl0, bl1, bl2, bl3, kl_base + row * 128 + swz);
                mma_16816(c[2 * g], qa_h[kd][0], qa_h[kd][1], qa_h[kd][2], qa_h[kd][3], bh0, bh1);
                mma_16816(c[2 * g], qa_l[kd][0], qa_l[kd][1], qa_l[kd][2], qa_l[kd][3], bh0, bh1);
                mma_16816(c[2 * g], qa_h[kd][0], qa_h[kd][1], qa_h[kd][2], qa_h[kd][3], bl0, bl1);
                mma_16816(c[2 * g + 1], qa_h[kd][0], qa_h[kd][1], qa_h[kd][2], qa_h[kd][3], bh2, bh3);
                mma_16816(c[2 * g + 1], qa_l[kd][0], qa_l[kd][1], qa_l[kd][2], qa_l[kd][3], bh2, bh3);
                mma_16816(c[2 * g + 1], qa_h[kd][0], qa_h[kd][1], qa_h[kd][2], qa_h[kd][3], bl2, bl3);
            }
        }

        // ---- softmax
        bool diag = (kt == qt);
        int kt64 = kt * 64;
        const unsigned char* pads_s = (const unsigned char*)(dyn_smem + AT_PADOFF + s * 64);
#pragma unroll
        for (int h2 = 0; h2 < 2; h2++) {
            int rowG = qt * 64 + wid * 16 + (lane >> 2) + h2 * 8;
            float mx = m2[h2];
#pragma unroll
            for (int t = 0; t < 8; t++) {
#pragma unroll
                for (int i = 0; i < 2; i++) {
                    int idx = h2 * 2 + i;
                    int cl = t * 8 + (lane & 3) * 2 + i;
                    float sv = c[t][idx];
                    if (pads_s[cl]) sv = -FLT_MAX;
                    if (diag && (kt64 + cl > rowG)) sv = -FLT_MAX;
                    c[t][idx] = sv;
                    mx = fmaxf(mx, sv);
                }
            }
            mx = fmaxf(mx, __shfl_xor_sync(0xFFFFFFFFu, mx, 1));
            mx = fmaxf(mx, __shfl_xor_sync(0xFFFFFFFFu, mx, 2));
            float scl = exp2poly((m2[h2] - mx) * LOG2E);
            float mL = mx * LOG2E;
            float rs = 0.f;
#pragma unroll
            for (int t = 0; t < 8; t++) {
#pragma unroll
                for (int i = 0; i < 2; i++) {
                    int idx = h2 * 2 + i;
                    float p = exp2poly(fmaf(c[t][idx], LOG2E, -mL));
                    c[t][idx] = p;
                    rs += p;
                }
            }
            rs += __shfl_xor_sync(0xFFFFFFFFu, rs, 1);
            rs += __shfl_xor_sync(0xFFFFFFFFu, rs, 2);
            l2[h2] = l2[h2] * scl + rs;
            m2[h2] = mx;
#pragma unroll
            for (int t = 0; t < 8; t++) {
                o[t][h2 * 2] *= scl;
                o[t][h2 * 2 + 1] *= scl;
            }
        }

        // ---- pack P -> hi/lo A fragments
        uint32_t pa_h[4][4], pa_l[4][4];
#pragma unroll
        for (int kc = 0; kc < 4; kc++) {
            uint32_t hp[4];
            hp[0] = pack_bf16(c[2 * kc][1], c[2 * kc][0]);
            hp[1] = pack_bf16(c[2 * kc][3], c[2 * kc][2]);
            hp[2] = pack_bf16(c[2 * kc + 1][1], c[2 * kc + 1][0]);
            hp[3] = pack_bf16(c[2 * kc + 1][3], c[2 * kc + 1][2]);
#pragma unroll
            for (int j = 0; j < 4; j++) {
                pa_h[kc][j] = hp[j];
                float vlo = c[2 * kc + (j >> 1)][(j & 1) * 2]     - __uint_as_float(hp[j] << 16);
                float vhi = c[2 * kc + (j >> 1)][(j & 1) * 2 + 1] - __uint_as_float(hp[j] & 0xFFFF0000u);
                pa_l[kc][j] = pack_bf16(vhi, vlo);
            }
        }

        // ---- O += P V (3-term)
#pragma unroll
        for (int kc = 0; kc < 4; kc++) {
#pragma unroll
            for (int g = 0; g < 4; g++) {
                int row = g * 16 + n_off;
                uint32_t swz = (((kc * 2 + kb) ^ (n_off & 7)) << 4);
                uint32_t bh0, bh1, bh2, bh3, bl0, bl1, bl2, bl3;
                ldmatrix_x4(bh0, bh1, bh2, bh3, vh_base + row * 128 + swz);
                ldmatrix_x4(bl0, bl1, bl2, bl3, vl_base + row * 128 + swz);
                mma_16816(o[2 * g], pa_h[kc][0], pa_h[kc][1], pa_h[kc][2], pa_h[kc][3], bh0, bh1);
                mma_16816(o[2 * g], pa_l[kc][0], pa_l[kc][1], pa_l[kc][2], pa_l[kc][3], bh0, bh1);
                mma_16816(o[2 * g], pa_h[kc][0], pa_h[kc][1], pa_h[kc][2], pa_h[kc][3], bl0, bl1);
                mma_16816(o[2 * g + 1], pa_h[kc][0], pa_h[kc][1], pa_h[kc][2], pa_h[kc][3], bh2, bh3);
                mma_16816(o[2 * g + 1], pa_l[kc][0], pa_l[kc][1], pa_l[kc][2], pa_l[kc][3], bh2, bh3);
                mma_16816(o[2 * g + 1], pa_h[kc][0], pa_h[kc][1], pa_h[kc][2], pa_h[kc][3], bl2, bl3);
            }
        }
        __syncthreads();
    }

    // ---- epilogue: Y = O / l
#pragma unroll
    for (int h2 = 0; h2 < 2; h2++) {
        float inv = 1.f / l2[h2];
        int token = b * SEQ + qt * 64 + wid * 16 + (lane >> 2) + h2 * 8;
        float* yrow = Y + (size_t)token * 1024 + h * 64 + (lane & 3) * 2;
#pragma unroll
        for (int t = 0; t < 8; t++) {
            *(float2*)(yrow + t * 8) =
                make_float2(o[t][h2 * 2] * inv, o[t][h2 * 2 + 1] * inv);
        }
    }
}

// ---------------------------------------------------------------------------
extern "C" void kernel_launch(void* const* d_in, const int* in_sizes, int n_in,
                              void* d_out, int out_size)
{
    const float*         x   = (const float*)d_in[0];
    const unsigned char* pad = (const unsigned char*)d_in[1];
    const float*         Wq  = (const float*)d_in[2];
    const float*         bq  = (const float*)d_in[3];
    const float*         Wk  = (const float*)d_in[4];
    const float*         bk  = (const float*)d_in[5];
    const float*         Wv  = (const float*)d_in[6];
    const float*         bv  = (const float*)d_in[7];
    const float*         Wo  = (const float*)d_in[8];
    const float*         bo  = (const float*)d_in[9];
    float*               out = (float*)d_out;

    void *vp, *yp, *x3p, *y3p, *wqp, *wkp, *wvp, *wop;
    void *qhp, *qlp, *khp, *klp, *vthp, *vtlp;
    cudaGetSymbolAddress(&vp, g_V);
    cudaGetSymbolAddress(&yp, g_Y);
    cudaGetSymbolAddress(&x3p, g_X3);
    cudaGetSymbolAddress(&y3p, g_Y3);
    cudaGetSymbolAddress(&wqp, g_W3q);
    cudaGetSymbolAddress(&wkp, g_W3k);
    cudaGetSymbolAddress(&wvp, g_W3v);
    cudaGetSymbolAddress(&wop, g_W3o);
    cudaGetSymbolAddress(&qhp, g_Qhi);
    cudaGetSymbolAddress(&qlp, g_Qlo);
    cudaGetSymbolAddress(&khp, g_Khi);
    cudaGetSymbolAddress(&klp, g_Klo);
    cudaGetSymbolAddress(&vthp, g_VThi);
    cudaGetSymbolAddress(&vtlp, g_VTlo);
    float* Vs = (float*)vp;
    float* Ys = (float*)yp;
    __nv_bfloat16* X3 = (__nv_bfloat16*)x3p;
    __nv_bfloat16* Y3 = (__nv_bfloat16*)y3p;
    __nv_bfloat16* W3q = (__nv_bfloat16*)wqp;
    __nv_bfloat16* W3k = (__nv_bfloat16*)wkp;
    __nv_bfloat16* W3v = (__nv_bfloat16*)wvp;
    __nv_bfloat16* W3o = (__nv_bfloat16*)wop;
    __nv_bfloat16* Qhi = (__nv_bfloat16*)qhp;
    __nv_bfloat16* Qlo = (__nv_bfloat16*)qlp;
    __nv_bfloat16* Khi = (__nv_bfloat16*)khp;
    __nv_bfloat16* Klo = (__nv_bfloat16*)klp;
    __nv_bfloat16* VThi = (__nv_bfloat16*)vthp;
    __nv_bfloat16* VTlo = (__nv_bfloat16*)vtlp;

    cudaFuncSetAttribute(gemm_bf16_mma, cudaFuncAttributeMaxDynamicSharedMemorySize, GEMM_SMEM);
    cudaFuncSetAttribute(attention_mma, cudaFuncAttributeMaxDynamicSharedMemorySize, AT_SMEM);

    convert_hilo3<<<(M_ROWS * 256) / 256, 256>>>(x, X3, 0);
    convert_hilo3<<<(D_MODEL * 256) / 256, 256>>>(Wq, g_W3q ? W3q : W3q, 1);
    convert_hilo3<<<(D_MODEL * 256) / 256, 256>>>(Wk, W3k, 1);
    convert_hilo3<<<(D_MODEL * 256) / 256, 256>>>(Wv, W3v, 1);
    convert_hilo3<<<(D_MODEL * 256) / 256, 256>>>(Wo, W3o, 1);

    // QKV projections: z=0 -> Q hi/lo (scaled 1/8), z=1 -> K hi/lo, z=2 -> V fp32
    dim3 qkv_grid(D_MODEL / GTN, M_ROWS / GTM, 3);
    gemm_bf16_mma<<<qkv_grid, 256, GEMM_SMEM>>>(
        X3, W3q, W3k, W3v, bq, bk, bv,
        nullptr, nullptr, Vs,
        Qhi, Khi, nullptr,
        Qlo, Klo, nullptr,
        0.125f, 1.f, 1.f);

    dim3 tr_grid(SEQ / 32, D_MODEL / 32, BATCH);
    transpose_v<<<tr_grid, 256>>>(Vs, VThi, VTlo);

    dim3 attn_grid(SEQ / 64, N_HEADS, BATCH);        // (32, 16, 4)
    attention_mma<<<attn_grid, 128, AT_SMEM>>>(Qhi, Qlo, Khi, Klo, VThi, VTlo, pad, Ys);

    convert_hilo3<<<(M_ROWS * 256) / 256, 256>>>(Ys, Y3, 0);

    dim3 o_grid(D_MODEL / GTN, M_ROWS / GTM, 1);
    gemm_bf16_mma<<<o_grid, 256, GEMM_SMEM>>>(
        Y3, W3o, W3o, W3o, bo, bo, bo,
        out, nullptr, nullptr,
        nullptr, nullptr, nullptr,
        nullptr, nullptr, nullptr,
        1.f, 1.f, 1.f);
}

// round 11
// speedup vs baseline: 6.5646x; 1.4032x over previous
#include <cuda_runtime.h>
#include <cuda_fp16.h>
#include <math.h>
#include <float.h>
#include <stdint.h>

#define D_MODEL 1024
#define N_HEADS 16
#define D_H 64
#define BATCH 4
#define SEQ 2048
#define M_ROWS (BATCH * SEQ)   // 8192
#define KK 2048                // 2-term split K: [hi|lo] . [hi|hi]
#define LOG2E 1.4426950408889634f

// ---------------- scratch (__device__ globals; alloc-free rule) -------------
__device__ float g_V[M_ROWS * D_MODEL];
__device__ float g_Y[M_ROWS * D_MODEL];
__device__ __half g_Qhi[M_ROWS * D_MODEL];
__device__ __half g_Qlo[M_ROWS * D_MODEL];
__device__ __half g_Khi[M_ROWS * D_MODEL];
__device__ __half g_VT[BATCH * N_HEADS * D_H * SEQ];
__device__ __half g_X2[M_ROWS * KK];
__device__ __half g_Y2[M_ROWS * KK];
__device__ __half g_W2q[D_MODEL * KK];
__device__ __half g_W2k[D_MODEL * KK];
__device__ __half g_W2v[D_MODEL * KK];
__device__ __half g_W2o[D_MODEL * KK];

// ---------------- PTX helpers ------------------------------------------------
__device__ __forceinline__ uint32_t smem_u32(const void* p) {
    uint32_t a;
    asm("{ .reg .u64 t; cvta.to.shared.u64 t, %1; cvt.u32.u64 %0, t; }" : "=r"(a) : "l"(p));
    return a;
}
__device__ __forceinline__ void cp_async16(uint32_t dst, const void* src) {
    asm volatile("cp.async.cg.shared.global [%0], [%1], 16;" :: "r"(dst), "l"(src) : "memory");
}
__device__ __forceinline__ void cp_async4(uint32_t dst, const void* src) {
    asm volatile("cp.async.ca.shared.global [%0], [%1], 4;" :: "r"(dst), "l"(src) : "memory");
}
__device__ __forceinline__ void cp_commit() {
    asm volatile("cp.async.commit_group;" ::: "memory");
}
template <int N> __device__ __forceinline__ void cp_wait() {
    asm volatile("cp.async.wait_group %0;" :: "n"(N) : "memory");
}
__device__ __forceinline__ void ldmatrix_x4(uint32_t& r0, uint32_t& r1, uint32_t& r2, uint32_t& r3,
                                            uint32_t addr) {
    asm volatile("ldmatrix.sync.aligned.m8n8.x4.shared.b16 {%0,%1,%2,%3}, [%4];"
                 : "=r"(r0), "=r"(r1), "=r"(r2), "=r"(r3) : "r"(addr));
}
__device__ __forceinline__ void mma_16816(float* d,
                                          uint32_t a0, uint32_t a1, uint32_t a2, uint32_t a3,
                                          uint32_t b0, uint32_t b1) {
    asm volatile(
        "mma.sync.aligned.m16n8k16.row.col.f32.f16.f16.f32 "
        "{%0,%1,%2,%3}, {%4,%5,%6,%7}, {%8,%9}, {%0,%1,%2,%3};"
        : "+f"(d[0]), "+f"(d[1]), "+f"(d[2]), "+f"(d[3])
        : "r"(a0), "r"(a1), "r"(a2), "r"(a3), "r"(b0), "r"(b1));
}
__device__ __forceinline__ uint32_t pack_f16(float hi, float lo) {
    uint32_t d;
    asm("cvt.rn.f16x2.f32 %0, %1, %2;" : "=r"(d) : "f"(hi), "f"(lo));
    return d;   // lo in bits [0:16), hi in [16:32)
}
// exp2 via FFMA only (no MUFU): t<=0 expected, clamps at -126.
__device__ __forceinline__ float exp2poly(float t) {
    t = fmaxf(t, -126.f);
    float r = t + 12582912.f;
    int e = __float_as_int(r) - 0x4B400000;
    float f = t - (r - 12582912.f);
    float p = 0.00133335581f;
    p = fmaf(p, f, 0.00961812911f);
    p = fmaf(p, f, 0.05550410866f);
    p = fmaf(p, f, 0.24022650695f);
    p = fmaf(p, f, 0.69314718056f);
    p = fmaf(p, f, 1.0f);
    return __int_as_float(__float_as_int(p) + (e << 23));
}

// ---------------- fp16 split conversions -------------------------------------
// A-side: row 1024 fp32 -> [hi | lo] fp16 (K=2048)
__global__ __launch_bounds__(256) void convert_f16_A(const float* __restrict__ in,
                                                     __half* __restrict__ out) {
    int idx4 = blockIdx.x * blockDim.x + threadIdx.x;
    int row = idx4 >> 8;
    int col = (idx4 & 255) << 2;
    float4 f = *(const float4*)(in + ((size_t)row << 10) + col);
    __half h[4], l[4];
    h[0] = __float2half(f.x); l[0] = __float2half(f.x - __half2float(h[0]));
    h[1] = __float2half(f.y); l[1] = __float2half(f.y - __half2float(h[1]));
    h[2] = __float2half(f.z); l[2] = __float2half(f.z - __half2float(h[2]));
    h[3] = __float2half(f.w); l[3] = __float2half(f.w - __half2float(h[3]));
    __half* base = out + (size_t)row * KK + col;
#pragma unroll
    for (int i = 0; i < 4; i++) { base[i] = h[i]; base[1024 + i] = l[i]; }
}
// B-side: row 1024 fp32 -> [hi | hi] fp16 (K=2048)
__global__ __launch_bounds__(256) void convert_f16_B(const float* __restrict__ in,
                                                     __half* __restrict__ out) {
    int idx4 = blockIdx.x * blockDim.x + threadIdx.x;
    int row = idx4 >> 8;
    int col = (idx4 & 255) << 2;
    float4 f = *(const float4*)(in + ((size_t)row << 10) + col);
    __half h[4];
    h[0] = __float2half(f.x); h[1] = __float2half(f.y);
    h[2] = __float2half(f.z); h[3] = __float2half(f.w);
    __half* base = out + (size_t)row * KK + col;
#pragma unroll
    for (int i = 0; i < 4; i++) { base[i] = h[i]; base[1024 + i] = h[i]; }
}

// ---------------- V transpose: g_V fp32 -> VT hi fp16 [bh][64][2048] ---------
__global__ __launch_bounds__(256) void transpose_v(const float* __restrict__ V,
                                                   __half* __restrict__ VT) {
    __shared__ float ts[32][33];
    int tx = threadIdx.x & 31, ty = threadIdx.x >> 5;
    int t0 = blockIdx.x * 32, c0 = blockIdx.y * 32, b = blockIdx.z;
#pragma unroll
    for (int i = 0; i < 4; i++)
        ts[ty + i * 8][tx] = V[(size_t)(b * SEQ + t0 + ty + i * 8) * 1024 + c0 + tx];
    __syncthreads();
#pragma unroll
    for (int i = 0; i < 4; i++) {
        int dm = c0 + ty + i * 8;
        float v = ts[tx][ty + i * 8];
        size_t o = ((size_t)(b * 16 + (dm >> 6)) * 64 + (dm & 63)) * SEQ + t0 + tx;
        VT[o] = __float2half(v);
    }
}

// ---------------- mma.sync fp16 NT GEMM --------------------------------------
#define GTM 128
#define GTN 128
#define GKC 64
#define NCHUNK (KK / GKC)          // 32
#define A_ST (GTM * 128)
#define B_ST (GTN * 128)
#define STAGE_BYTES (A_ST + B_ST)
#define NSTAGE 3
#define GEMM_SMEM (NSTAGE * STAGE_BYTES + 1024)

extern __shared__ char dyn_smem[];

__global__ __launch_bounds__(256, 2)
void gemm_f16_mma(const __half* __restrict__ A2,
                  const __half* __restrict__ B0, const __half* __restrict__ B1,
                  const __half* __restrict__ B2w,
                  const float* __restrict__ bias0, const float* __restrict__ bias1,
                  const float* __restrict__ bias2,
                  float* cf0, float* cf1, float* cf2,
                  __half* chi0, __half* chi1, __half* chi2,
                  __half* clo0, __half* clo1, __half* clo2,
                  float sc0, float sc1, float sc2)
{
    const __half* B2;
    const float* bias;
    float* cf; __half *chi, *clo; float scale;
    if (blockIdx.z == 0)      { B2 = B0; bias = bias0; cf = cf0; chi = chi0; clo = clo0; scale = sc0; }
    else if (blockIdx.z == 1) { B2 = B1; bias = bias1; cf = cf1; chi = chi1; clo = clo1; scale = sc1; }
    else                      { B2 = B2w; bias = bias2; cf = cf2; chi = chi2; clo = clo2; scale = sc2; }

    uint32_t smem_base = smem_u32(dyn_smem);
    uint32_t data0 = (smem_base + 1023) & ~1023u;

    int tid = threadIdx.x;
    int wid = tid >> 5;
    int lane = tid & 31;
    int bm = blockIdx.y * GTM;
    int bn = blockIdx.x * GTN;
    int wm = (wid & 3) * 32;
    int wn = (wid >> 2) * 64;

    int ar = lane & 15;
    int ac = lane >> 4;
    int n_off = ((lane >> 4) << 3) + (lane & 7);
    int kb = (lane >> 3) & 1;

    float d[2][8][4];
#pragma unroll
    for (int i = 0; i < 2; i++)
#pragma unroll
        for (int j = 0; j < 8; j++)
#pragma unroll
            for (int q = 0; q < 4; q++) d[i][j][q] = 0.f;

    auto load_chunk = [&](int c, int s) {
        uint32_t abase = data0 + s * STAGE_BYTES;
        uint32_t bbase = abase + A_ST;
        const __half* Ac = A2 + (size_t)bm * KK + c * GKC;
        const __half* Bc = B2 + (size_t)bn * KK + c * GKC;
#pragma unroll
        for (int t = 0; t < 4; t++) {
            int sgi = tid + t * 256;
            int row = sgi >> 3, seg = sgi & 7;
            cp_async16(abase + row * 128 + ((seg ^ (row & 7)) << 4),
                       Ac + (size_t)row * KK + seg * 8);
        }
#pragma unroll
        for (int t = 0; t < 4; t++) {
            int sgi = tid + t * 256;
            int row = sgi >> 3, seg = sgi & 7;
            cp_async16(bbase + row * 128 + ((seg ^ (row & 7)) << 4),
                       Bc + (size_t)row * KK + seg * 8);
        }
        cp_commit();
    };

    load_chunk(0, 0);
    load_chunk(1, 1);

    for (int i = 0; i < NCHUNK; i++) {
        int s = i % NSTAGE;
        if (i == NCHUNK - 1) cp_wait<0>(); else cp_wait<1>();
        __syncthreads();
        if (i + 2 < NCHUNK) load_chunk(i + 2, (i + 2) % NSTAGE);

        uint32_t abase = data0 + s * STAGE_BYTES;
        uint32_t bbase = abase + A_ST;
#pragma unroll
        for (int ks = 0; ks < 4; ks++) {
            uint32_t af[2][4];
#pragma unroll
            for (int mf = 0; mf < 2; mf++) {
                int row = wm + mf * 16 + ar;
                uint32_t addr = abase + row * 128 + (((ks * 2 + ac) ^ (ar & 7)) << 4);
                ldmatrix_x4(af[mf][0], af[mf][1], af[mf][2], af[mf][3], addr);
            }
#pragma unroll
            for (int nf = 0; nf < 4; nf++) {
                int row = wn + nf * 16 + n_off;
                uint32_t addr = bbase + row * 128 + (((ks * 2 + kb) ^ (n_off & 7)) << 4);
                uint32_t b00, b01, b10, b11;
                ldmatrix_x4(b00, b01, b10, b11, addr);
#pragma unroll
                for (int mf = 0; mf < 2; mf++) {
                    mma_16816(d[mf][2 * nf], af[mf][0], af[mf][1], af[mf][2], af[mf][3], b00, b01);
                    mma_16816(d[mf][2 * nf + 1], af[mf][0], af[mf][1], af[mf][2], af[mf][3], b10, b11);
                }
            }
        }
        // NOTE: no trailing __syncthreads needed with 3-stage pipeline:
        // the next overwrite of stage s happens only after the next top-of-loop barrier.
    }

#pragma unroll
    for (int mf = 0; mf < 2; mf++) {
        int m0 = bm + wm + mf * 16 + (lane >> 2);
#pragma unroll
        for (int n8 = 0; n8 < 8; n8++) {
            int n0 = bn + wn + n8 * 8 + (lane & 3) * 2;
            float b0 = bias[n0], b1 = bias[n0 + 1];
            float v0 = (d[mf][n8][0] + b0) * scale;
            float v1 = (d[mf][n8][1] + b1) * scale;
            float v2 = (d[mf][n8][2] + b0) * scale;
            float v3 = (d[mf][n8][3] + b1) * scale;
            if (cf) {
                *(float2*)(cf + (size_t)m0 * D_MODEL + n0) = make_float2(v0, v1);
                *(float2*)(cf + (size_t)(m0 + 8) * D_MODEL + n0) = make_float2(v2, v3);
            }
            if (chi) {
                uint32_t h01 = pack_f16(v1, v0);
                uint32_t h23 = pack_f16(v3, v2);
                *(uint32_t*)(chi + (size_t)m0 * D_MODEL + n0) = h01;
                *(uint32_t*)(chi + (size_t)(m0 + 8) * D_MODEL + n0) = h23;
                if (clo) {
                    __half2 a01 = *reinterpret_cast<__half2*>(&h01);
                    __half2 a23 = *reinterpret_cast<__half2*>(&h23);
                    float r0 = v0 - __half2float(__low2half(a01));
                    float r1 = v1 - __half2float(__high2half(a01));
                    float r2 = v2 - __half2float(__low2half(a23));
                    float r3 = v3 - __half2float(__high2half(a23));
                    *(uint32_t*)(clo + (size_t)m0 * D_MODEL + n0) = pack_f16(r1, r0);
                    *(uint32_t*)(clo + (size_t)(m0 + 8) * D_MODEL + n0) = pack_f16(r3, r2);
                }
            }
        }
    }
}

// ---------------- tensor-core flash attention (fp16 2-term) ------------------
// CTA: 64 queries of one (b,h); 4 warps x 16 rows. 64-key tiles, 2-stage.
// smem: [0,8K) Qhi  [8K,16K) Qlo
//       stage s at 16K + s*16K: Khi (8K), Vhi (8K)
//       pads at 48K + s*64
#define AT_STAGE0 16384
#define AT_PADOFF (16384 + 32768)
#define AT_SMEM (AT_PADOFF + 128)

__global__ __launch_bounds__(128, 3)
void attention_mma(const __half* __restrict__ Qhi, const __half* __restrict__ Qlo,
                   const __half* __restrict__ Khi, const __half* __restrict__ VT,
                   const unsigned char* __restrict__ pad, float* __restrict__ Y)
{
    uint32_t sb = smem_u32(dyn_smem);
    int tid = threadIdx.x;
    int wid = tid >> 5;
    int lane = tid & 31;
    int qt = (int)(gridDim.x - 1 - blockIdx.x);   // big tiles first
    int h = blockIdx.y, b = blockIdx.z;
    int nkt = qt + 1;

    int ar = lane & 15, ac = lane >> 4;
    int n_off = ((lane >> 4) << 3) + (lane & 7);
    int kb = (lane >> 3) & 1;

    // --- Q load (hi/lo), group 0
    {
        const __half* srcs[2] = {Qhi, Qlo};
#pragma unroll
        for (int a = 0; a < 2; a++) {
            uint32_t base = sb + a * 8192;
            const __half* src = srcs[a] + (size_t)(b * SEQ + qt * 64) * 1024 + h * 64;
#pragma unroll
            for (int t = 0; t < 4; t++) {
                int sgi = tid + t * 128;
                int row = sgi >> 3, seg = sgi & 7;
                cp_async16(base + row * 128 + ((seg ^ (row & 7)) << 4),
                           src + (size_t)row * 1024 + seg * 8);
            }
        }
        cp_commit();
    }

    auto load_tile = [&](int kt, int s) {
        uint32_t stb = sb + AT_STAGE0 + s * 16384;
        {
            const __half* src = Khi + (size_t)(b * SEQ + kt * 64) * 1024 + h * 64;
#pragma unroll
            for (int t = 0; t < 4; t++) {
                int sgi = tid + t * 128;
                int row = sgi >> 3, seg = sgi & 7;
                cp_async16(stb + row * 128 + ((seg ^ (row & 7)) << 4),
                           src + (size_t)row * 1024 + seg * 8);
            }
        }
        {
            const __half* src = VT + (size_t)(b * 16 + h) * 64 * SEQ + kt * 64;
#pragma unroll
            for (int t = 0; t < 4; t++) {
                int sgi = tid + t * 128;
                int row = sgi >> 3, seg = sgi & 7;
                cp_async16(stb + 8192 + row * 128 + ((seg ^ (row & 7)) << 4),
                           src + (size_t)row * SEQ + seg * 8);
            }
        }
        if (tid < 16)
            cp_async4(sb + AT_PADOFF + s * 64 + tid * 4, pad + b * SEQ + kt * 64 + tid * 4);
        cp_commit();
    };

    load_tile(0, 0);
    cp_wait<1>();            // Q done
    __syncthreads();

    // Q fragments (hi and lo)
    uint32_t qa_h[4][4], qa_l[4][4];
#pragma unroll
    for (int kd = 0; kd < 4; kd++) {
        int row = wid * 16 + ar;
        uint32_t swz = (((kd * 2 + ac) ^ (ar & 7)) << 4);
        ldmatrix_x4(qa_h[kd][0], qa_h[kd][1], qa_h[kd][2], qa_h[kd][3], sb + row * 128 + swz);
        ldmatrix_x4(qa_l[kd][0], qa_l[kd][1], qa_l[kd][2], qa_l[kd][3], sb + 8192 + row * 128 + swz);
    }

    float o[8][4];
#pragma unroll
    for (int t = 0; t < 8; t++)
#pragma unroll
        for (int q = 0; q < 4; q++) o[t][q] = 0.f;
    float m2[2] = {-FLT_MAX, -FLT_MAX};
    float l2[2] = {0.f, 0.f};

    for (int kt = 0; kt < nkt; kt++) {
        int s = kt & 1;
        if (kt + 1 < nkt) { load_tile(kt + 1, s ^ 1); cp_wait<1>(); }
        else              { cp_wait<0>(); }
        __syncthreads();

        uint32_t kh_base = sb + AT_STAGE0 + s * 16384;
        uint32_t vh_base = kh_base + 8192;

        // ---- S = Q K^T (2-term: Qhi.Khi + Qlo.Khi)
        float c[8][4];
#pragma unroll
        for (int t = 0; t < 8; t++)
#pragma unroll
            for (int q = 0; q < 4; q++) c[t][q] = 0.f;
#pragma unroll
        for (int kd = 0; kd < 4; kd++) {
#pragma unroll
            for (int g = 0; g < 4; g++) {
                int row = g * 16 + n_off;
                uint32_t swz = (((kd * 2 + kb) ^ (n_off & 7)) << 4);
                uint32_t bh0, bh1, bh2, bh3;
                ldmatrix_x4(bh0, bh1, bh2, bh3, kh_base + row * 128 + swz);
                mma_16816(c[2 * g], qa_h[kd][0], qa_h[kd][1], qa_h[kd][2], qa_h[kd][3], bh0, bh1);
                mma_16816(c[2 * g], qa_l[kd][0], qa_l[kd][1], qa_l[kd][2], qa_l[kd][3], bh0, bh1);
                mma_16816(c[2 * g + 1], qa_h[kd][0], qa_h[kd][1], qa_h[kd][2], qa_h[kd][3], bh2, bh3);
                mma_16816(c[2 * g + 1], qa_l[kd][0], qa_l[kd][1], qa_l[kd][2], qa_l[kd][3], bh2, bh3);
            }
        }

        // ---- softmax
        bool diag = (kt == qt);
        int kt64 = kt * 64;
        const unsigned char* pads_s = (const unsigned char*)(dyn_smem + AT_PADOFF + s * 64);
#pragma unroll
        for (int h2 = 0; h2 < 2; h2++) {
            int rowG = qt * 64 + wid * 16 + (lane >> 2) + h2 * 8;
            float mx = m2[h2];
#pragma unroll
            for (int t = 0; t < 8; t++) {
#pragma unroll
                for (int i = 0; i < 2; i++) {
                    int idx = h2 * 2 + i;
                    int cl = t * 8 + (lane & 3) * 2 + i;
                    float sv = c[t][idx];
                    if (pads_s[cl]) sv = -FLT_MAX;
                    if (diag && (kt64 + cl > rowG)) sv = -FLT_MAX;
                    c[t][idx] = sv;
                    mx = fmaxf(mx, sv);
                }
            }
            mx = fmaxf(mx, __shfl_xor_sync(0xFFFFFFFFu, mx, 1));
            mx = fmaxf(mx, __shfl_xor_sync(0xFFFFFFFFu, mx, 2));
            float scl = exp2poly((m2[h2] - mx) * LOG2E);
            float mL = mx * LOG2E;
            float rs = 0.f;
#pragma unroll
            for (int t = 0; t < 8; t++) {
#pragma unroll
                for (int i = 0; i < 2; i++) {
                    int idx = h2 * 2 + i;
                    float p = exp2poly(fmaf(c[t][idx], LOG2E, -mL));
                    c[t][idx] = p;
                    rs += p;
                }
            }
            rs += __shfl_xor_sync(0xFFFFFFFFu, rs, 1);
            rs += __shfl_xor_sync(0xFFFFFFFFu, rs, 2);
            l2[h2] = l2[h2] * scl + rs;
            m2[h2] = mx;
#pragma unroll
            for (int t = 0; t < 8; t++) {
                o[t][h2 * 2] *= scl;
                o[t][h2 * 2 + 1] *= scl;
            }
        }

        // ---- pack P -> hi/lo fp16 A fragments
        uint32_t pa_h[4][4], pa_l[4][4];
#pragma unroll
        for (int kc = 0; kc < 4; kc++) {
            uint32_t hp[4];
            hp[0] = pack_f16(c[2 * kc][1], c[2 * kc][0]);
            hp[1] = pack_f16(c[2 * kc][3], c[2 * kc][2]);
            hp[2] = pack_f16(c[2 * kc + 1][1], c[2 * kc + 1][0]);
            hp[3] = pack_f16(c[2 * kc + 1][3], c[2 * kc + 1][2]);
#pragma unroll
            for (int j = 0; j < 4; j++) {
                pa_h[kc][j] = hp[j];
                __half2 hj = *reinterpret_cast<__half2*>(&hp[j]);
                float vlo = c[2 * kc + (j >> 1)][(j & 1) * 2]     - __half2float(__low2half(hj));
                float vhi = c[2 * kc + (j >> 1)][(j & 1) * 2 + 1] - __half2float(__high2half(hj));
                pa_l[kc][j] = pack_f16(vhi, vlo);
            }
        }

        // ---- O += P V (2-term: Phi.Vhi + Plo.Vhi)
#pragma unroll
        for (int kc = 0; kc < 4; kc++) {
#pragma unroll
            for (int g = 0; g < 4; g++) {
                int row = g * 16 + n_off;
                uint32_t swz = (((kc * 2 + kb) ^ (n_off & 7)) << 4);
                uint32_t bh0, bh1, bh2, bh3;
                ldmatrix_x4(bh0, bh1, bh2, bh3, vh_base + row * 128 + swz);
                mma_16816(o[2 * g], pa_h[kc][0], pa_h[kc][1], pa_h[kc][2], pa_h[kc][3], bh0, bh1);
                mma_16816(o[2 * g], pa_l[kc][0], pa_l[kc][1], pa_l[kc][2], pa_l[kc][3], bh0, bh1);
                mma_16816(o[2 * g + 1], pa_h[kc][0], pa_h[kc][1], pa_h[kc][2], pa_h[kc][3], bh2, bh3);
                mma_16816(o[2 * g + 1], pa_l[kc][0], pa_l[kc][1], pa_l[kc][2], pa_l[kc][3], bh2, bh3);
            }
        }
        __syncthreads();
    }

    // ---- epilogue: Y = O / l
#pragma unroll
    for (int h2 = 0; h2 < 2; h2++) {
        float inv = 1.f / l2[h2];
        int token = b * SEQ + qt * 64 + wid * 16 + (lane >> 2) + h2 * 8;
        float* yrow = Y + (size_t)token * 1024 + h * 64 + (lane & 3) * 2;
#pragma unroll
        for (int t = 0; t < 8; t++) {
            *(float2*)(yrow + t * 8) =
                make_float2(o[t][h2 * 2] * inv, o[t][h2 * 2 + 1] * inv);
        }
    }
}

// ---------------------------------------------------------------------------
extern "C" void kernel_launch(void* const* d_in, const int* in_sizes, int n_in,
                              void* d_out, int out_size)
{
    const float*         x   = (const float*)d_in[0];
    const unsigned char* pad = (const unsigned char*)d_in[1];
    const float*         Wq  = (const float*)d_in[2];
    const float*         bq  = (const float*)d_in[3];
    const float*         Wk  = (const float*)d_in[4];
    const float*         bk  = (const float*)d_in[5];
    const float*         Wv  = (const float*)d_in[6];
    const float*         bv  = (const float*)d_in[7];
    const float*         Wo  = (const float*)d_in[8];
    const float*         bo  = (const float*)d_in[9];
    float*               out = (float*)d_out;

    void *vp, *yp, *x2p, *y2p, *wqp, *wkp, *wvp, *wop, *qhp, *qlp, *khp, *vtp;
    cudaGetSymbolAddress(&vp, g_V);
    cudaGetSymbolAddress(&yp, g_Y);
    cudaGetSymbolAddress(&x2p, g_X2);
    cudaGetSymbolAddress(&y2p, g_Y2);
    cudaGetSymbolAddress(&wqp, g_W2q);
    cudaGetSymbolAddress(&wkp, g_W2k);
    cudaGetSymbolAddress(&wvp, g_W2v);
    cudaGetSymbolAddress(&wop, g_W2o);
    cudaGetSymbolAddress(&qhp, g_Qhi);
    cudaGetSymbolAddress(&qlp, g_Qlo);
    cudaGetSymbolAddress(&khp, g_Khi);
    cudaGetSymbolAddress(&vtp, g_VT);
    float* Vs = (float*)vp;
    float* Ys = (float*)yp;
    __half* X2 = (__half*)x2p;
    __half* Y2 = (__half*)y2p;
    __half* W2q = (__half*)wqp;
    __half* W2k = (__half*)wkp;
    __half* W2v = (__half*)wvp;
    __half* W2o = (__half*)wop;
    __half* Qhi = (__half*)qhp;
    __half* Qlo = (__half*)qlp;
    __half* Khi = (__half*)khp;
    __half* VT  = (__half*)vtp;

    cudaFuncSetAttribute(gemm_f16_mma, cudaFuncAttributeMaxDynamicSharedMemorySize, GEMM_SMEM);
    cudaFuncSetAttribute(attention_mma, cudaFuncAttributeMaxDynamicSharedMemorySize, AT_SMEM);

    convert_f16_A<<<(M_ROWS * 256) / 256, 256>>>(x, X2);
    convert_f16_B<<<(D_MODEL * 256) / 256, 256>>>(Wq, W2q);
    convert_f16_B<<<(D_MODEL * 256) / 256, 256>>>(Wk, W2k);
    convert_f16_B<<<(D_MODEL * 256) / 256, 256>>>(Wv, W2v);
    convert_f16_B<<<(D_MODEL * 256) / 256, 256>>>(Wo, W2o);

    // QKV: z=0 -> Q hi/lo fp16 (scaled 1/8), z=1 -> K hi fp16, z=2 -> V fp32
    dim3 qkv_grid(D_MODEL / GTN, M_ROWS / GTM, 3);
    gemm_f16_mma<<<qkv_grid, 256, GEMM_SMEM>>>(
        X2, W2q, W2k, W2v, bq, bk, bv,
        nullptr, nullptr, Vs,
        Qhi, Khi, nullptr,
        Qlo, nullptr, nullptr,
        0.125f, 1.f, 1.f);

    dim3 tr_grid(SEQ / 32, D_MODEL / 32, BATCH);
    transpose_v<<<tr_grid, 256>>>(Vs, VT);

    dim3 attn_grid(SEQ / 64, N_HEADS, BATCH);        // (32, 16, 4)
    attention_mma<<<attn_grid, 128, AT_SMEM>>>(Qhi, Qlo, Khi, VT, pad, Ys);

    convert_f16_A<<<(M_ROWS * 256) / 256, 256>>>(Ys, Y2);

    dim3 o_grid(D_MODEL / GTN, M_ROWS / GTM, 1);
    gemm_f16_mma<<<o_grid, 256, GEMM_SMEM>>>(
        Y2, W2o, W2o, W2o, bo, bo, bo,
        out, nullptr, nullptr,
        nullptr, nullptr, nullptr,
        nullptr, nullptr, nullptr,
        1.f, 1.f, 1.f);
}